// round 1
// baseline (speedup 1.0000x reference)
#include <cuda_runtime.h>
#include <cstdint>

// GPTQ 4-bit fused dequant + SGEMM (fp32).
// x:       [M=8192, K=4096] fp32 (flattened [4,2048,4096])
// qweight: [K/8=512, N=4096] int32  (8 nibbles along K per word)
// qzeros:  [G=32, N/8=512]   int32  (8 nibbles along N per word), stored zero-1
// scales:  [G=32, N=4096]    fp32
// bias:    [N=4096]          fp32
// out:     [M, N]            fp32
//
// W[k,o] = scales[k/128, o] * (nib(qweight[k/8,o], k%8) - (nib(qzeros[k/128,o/8], o%8) + 1))

#define KDIM 4096
#define NDIM 4096
#define GROUPSZ 128
#define BM 128
#define BN 128
#define BK 16
#define TM 8
#define TN 8
#define NTHREADS 256

__global__ __launch_bounds__(NTHREADS, 2)
void gptq_gemm_f32(const float* __restrict__ x,
                   const int*   __restrict__ qw,
                   const int*   __restrict__ qz,
                   const float* __restrict__ sc,
                   const float* __restrict__ bias,
                   float* __restrict__ out)
{
    __shared__ float As[BK][BM];        // A tile, transposed (K-major rows)
    __shared__ float Bs[BK][BN];        // dequantized W tile

    const int bm = blockIdx.y * BM;
    const int bn = blockIdx.x * BN;
    const int tid = threadIdx.x;
    const int tx = tid & 15;            // 16 threads across N
    const int ty = tid >> 4;            // 16 threads across M

    float acc[TM][TN];
    #pragma unroll
    for (int i = 0; i < TM; i++)
        #pragma unroll
        for (int j = 0; j < TN; j++)
            acc[i][j] = 0.0f;

    // B-tile dequant mapping: 256 threads -> 128 columns x 2 qweight words
    const int bcol  = tid >> 1;         // 0..127: column within tile
    const int bhalf = tid & 1;          // which of the 2 int32 words (8 k's each)
    const int ocol  = bn + bcol;        // global output column

    for (int k0 = 0; k0 < KDIM; k0 += BK) {
        // ---- load A tile (128 x 16 fp32) via float4, store transposed ----
        #pragma unroll
        for (int i = 0; i < 2; i++) {
            int f   = tid * 2 + i;          // 0..511 float4 slots
            int row = f >> 2;               // 0..127
            int c4  = (f & 3) << 2;         // 0,4,8,12
            float4 v = *reinterpret_cast<const float4*>(
                &x[(size_t)(bm + row) * KDIM + k0 + c4]);
            As[c4 + 0][row] = v.x;
            As[c4 + 1][row] = v.y;
            As[c4 + 2][row] = v.z;
            As[c4 + 3][row] = v.w;
        }

        // ---- dequantize B tile (16 x 128) ----
        {
            const int g = k0 >> 7;                      // k-group (GROUPSZ=128)
            const float s = sc[g * NDIM + ocol];
            const int zword = qz[g * (NDIM / 8) + (ocol >> 3)];
            const float zp1 = (float)(((zword >> ((ocol & 7) * 4)) & 15) + 1);
            const float offs = -s * zp1;                // s*(q - z) = s*q + offs
            const int w = qw[((k0 >> 3) + bhalf) * NDIM + ocol];
            #pragma unroll
            for (int j = 0; j < 8; j++) {
                int q = (w >> (j * 4)) & 15;
                Bs[bhalf * 8 + j][bcol] = fmaf(s, (float)q, offs);
            }
        }
        __syncthreads();

        // ---- 8x8 microtile FFMA ----
        #pragma unroll
        for (int kk = 0; kk < BK; kk++) {
            float ra[TM], rb[TN];
            float4 a0 = *reinterpret_cast<const float4*>(&As[kk][ty * TM]);
            float4 a1 = *reinterpret_cast<const float4*>(&As[kk][ty * TM + 4]);
            ra[0] = a0.x; ra[1] = a0.y; ra[2] = a0.z; ra[3] = a0.w;
            ra[4] = a1.x; ra[5] = a1.y; ra[6] = a1.z; ra[7] = a1.w;
            float4 b0 = *reinterpret_cast<const float4*>(&Bs[kk][tx * TN]);
            float4 b1 = *reinterpret_cast<const float4*>(&Bs[kk][tx * TN + 4]);
            rb[0] = b0.x; rb[1] = b0.y; rb[2] = b0.z; rb[3] = b0.w;
            rb[4] = b1.x; rb[5] = b1.y; rb[6] = b1.z; rb[7] = b1.w;
            #pragma unroll
            for (int i = 0; i < TM; i++)
                #pragma unroll
                for (int j = 0; j < TN; j++)
                    acc[i][j] = fmaf(ra[i], rb[j], acc[i][j]);
        }
        __syncthreads();
    }

    // ---- epilogue: add bias, vectorized store ----
    #pragma unroll
    for (int i = 0; i < TM; i++) {
        int row = bm + ty * TM + i;
        #pragma unroll
        for (int j = 0; j < TN; j += 4) {
            int col = bn + tx * TN + j;
            float4 v;
            v.x = acc[i][j + 0] + bias[col + 0];
            v.y = acc[i][j + 1] + bias[col + 1];
            v.z = acc[i][j + 2] + bias[col + 2];
            v.w = acc[i][j + 3] + bias[col + 3];
            *reinterpret_cast<float4*>(&out[(size_t)row * NDIM + col]) = v;
        }
    }
}

extern "C" void kernel_launch(void* const* d_in, const int* in_sizes, int n_in,
                              void* d_out, int out_size)
{
    const float* x    = (const float*)d_in[0];
    const int*   qw   = (const int*)  d_in[1];
    const int*   qz   = (const int*)  d_in[2];
    const float* sc   = (const float*)d_in[3];
    const float* bias = (const float*)d_in[4];
    float*       out  = (float*)d_out;

    const int M = in_sizes[0] / KDIM;   // 8192

    dim3 grid(NDIM / BN, M / BM);       // (32, 64)
    gptq_gemm_f32<<<grid, NTHREADS>>>(x, qw, qz, sc, bias, out);
}

// round 3
// speedup vs baseline: 3.0460x; 3.0460x over previous
#include <cuda_runtime.h>
#include <cuda_bf16.h>
#include <cstdint>

// GPTQ 4-bit linear via warp-level bf16 mma.sync (sm_100 baseline-PTX safe).
//   Pass 1: split x (fp32) -> x_hi + x_lo (bf16), pre-tiled + SW128-swizzled.
//   Pass 2: dequant W = s*(q-z) -> W_hi + W_lo (bf16), [N,K], pre-tiled + swizzled.
//   Pass 3: GEMM with K concatenated over 3 segments:
//           y = x_hi@W_hi + x_hi@W_lo + x_lo@W_hi + bias   (x_lo@W_lo ~ 2^-18, dropped)

#define KDIM 4096
#define NDIM 4096
#define MMAX 8192
#define BM 128
#define BN 128
#define BK 64
#define STAGES 4
#define NTHREADS 256
#define KTILES (KDIM / BK)            // 64 k-tiles per segment
#define NTILES (3 * KTILES)           // 192 pipeline iterations
#define A_TILE_BYTES (BM * BK * 2)    // 16384
#define B_TILE_BYTES (BN * BK * 2)    // 16384
#define STAGE_BYTES (A_TILE_BYTES + B_TILE_BYTES)
#define SMEM_HDR 1024
#define SMEM_TOTAL (SMEM_HDR + STAGES * STAGE_BYTES)   // 132096

// Scratch: pre-tiled A tiles [Mtiles][KTILES][128x64 bf16], B tiles [Ntiles][KTILES][128x64 bf16]
__device__ __align__(1024) __nv_bfloat16 g_xhi[(size_t)MMAX * KDIM];
__device__ __align__(1024) __nv_bfloat16 g_xlo[(size_t)MMAX * KDIM];
__device__ __align__(1024) __nv_bfloat16 g_whi[(size_t)NDIM * KDIM];
__device__ __align__(1024) __nv_bfloat16 g_wlo[(size_t)NDIM * KDIM];

__device__ __forceinline__ uint32_t swz128(uint32_t off) {
    return off ^ ((off >> 3) & 0x70);
}
__device__ __forceinline__ uint32_t smem_u32(const void* p) {
    uint32_t a;
    asm("{ .reg .u64 t; cvta.to.shared.u64 t, %1; cvt.u32.u64 %0, t; }" : "=r"(a) : "l"(p));
    return a;
}
__device__ __forceinline__ void mbar_init(uint32_t mbar, uint32_t count) {
    asm volatile("mbarrier.init.shared.b64 [%0], %1;" :: "r"(mbar), "r"(count) : "memory");
}
__device__ __forceinline__ void mbar_expect_tx(uint32_t mbar, uint32_t bytes) {
    asm volatile("mbarrier.arrive.expect_tx.shared.b64 _, [%0], %1;" :: "r"(mbar), "r"(bytes) : "memory");
}
__device__ __forceinline__ void mbar_arrive(uint32_t mbar) {
    asm volatile("mbarrier.arrive.shared.b64 _, [%0];" :: "r"(mbar) : "memory");
}
__device__ __forceinline__ void mbar_wait(uint32_t mbar, uint32_t parity) {
    asm volatile(
        "{\n\t.reg .pred P;\n\t"
        "WAIT_%=:\n\t"
        "mbarrier.try_wait.parity.acquire.cta.shared::cta.b64 P, [%0], %1, 0x989680;\n\t"
        "@!P bra WAIT_%=;\n\t}"
        :: "r"(mbar), "r"(parity) : "memory");
}
__device__ __forceinline__ void bulk_g2s(uint32_t dst, const void* src, uint32_t bytes, uint32_t mbar) {
    asm volatile(
        "cp.async.bulk.shared::cluster.global.mbarrier::complete_tx::bytes [%0], [%1], %2, [%3];"
        :: "r"(dst), "l"(src), "r"(bytes), "r"(mbar) : "memory");
}
__device__ __forceinline__ void ldsm_x4(uint32_t* r, uint32_t addr) {
    asm volatile("ldmatrix.sync.aligned.m8n8.x4.shared.b16 {%0,%1,%2,%3}, [%4];"
                 : "=r"(r[0]), "=r"(r[1]), "=r"(r[2]), "=r"(r[3]) : "r"(addr));
}
__device__ __forceinline__ void mma_16816(float* c, const uint32_t* a, const uint32_t* b) {
    asm volatile(
        "mma.sync.aligned.m16n8k16.row.col.f32.bf16.bf16.f32 "
        "{%0,%1,%2,%3}, {%4,%5,%6,%7}, {%8,%9}, {%0,%1,%2,%3};"
        : "+f"(c[0]), "+f"(c[1]), "+f"(c[2]), "+f"(c[3])
        : "r"(a[0]), "r"(a[1]), "r"(a[2]), "r"(a[3]), "r"(b[0]), "r"(b[1]));
}

// ---------------------------------------------------------------------------
// Pass 1: split x into bf16 hi/lo, pre-tiled + swizzled
// ---------------------------------------------------------------------------
__global__ void split_x(const float* __restrict__ x, int M) {
    size_t idx = (size_t)blockIdx.x * blockDim.x + threadIdx.x;  // one per 8 elems
    size_t total = (size_t)M * KDIM / 8;
    if (idx >= total) return;
    int m  = (int)(idx >> 9);          // KDIM/8 = 512 chunks/row
    int k0 = ((int)idx & 511) << 3;

    const float* src = x + (size_t)m * KDIM + k0;
    float4 v0 = *reinterpret_cast<const float4*>(src);
    float4 v1 = *reinterpret_cast<const float4*>(src + 4);
    float v[8] = {v0.x, v0.y, v0.z, v0.w, v1.x, v1.y, v1.z, v1.w};

    union { __nv_bfloat16 h[8]; uint4 u; } hi, lo;
    #pragma unroll
    for (int j = 0; j < 8; j++) {
        __nv_bfloat16 h = __float2bfloat16_rn(v[j]);
        hi.h[j] = h;
        lo.h[j] = __float2bfloat16_rn(v[j] - __bfloat162float(h));
    }

    size_t off = ((size_t)(m >> 7) * KTILES + (k0 >> 6)) * A_TILE_BYTES
               + swz128((uint32_t)((m & 127) * 128 + (k0 & 63) * 2));
    *reinterpret_cast<uint4*>(reinterpret_cast<char*>(g_xhi) + off) = hi.u;
    *reinterpret_cast<uint4*>(reinterpret_cast<char*>(g_xlo) + off) = lo.u;
}

// ---------------------------------------------------------------------------
// Pass 2: dequant W -> bf16 hi/lo, transposed [N,K], pre-tiled + swizzled
// ---------------------------------------------------------------------------
__global__ void dequant_w(const int* __restrict__ qw, const int* __restrict__ qz,
                          const float* __restrict__ sc) {
    int idx = blockIdx.x * blockDim.x + threadIdx.x;   // one per qweight word
    int kw = idx >> 12;                 // k/8: 0..511
    int n  = idx & 4095;
    int g  = kw >> 4;                   // k/128
    float s = sc[g * NDIM + n];
    int z = ((qz[g * (NDIM / 8) + (n >> 3)] >> ((n & 7) * 4)) & 15) + 1;
    int w = qw[kw * NDIM + n];

    union { __nv_bfloat16 h[8]; uint4 u; } hi, lo;
    #pragma unroll
    for (int j = 0; j < 8; j++) {
        int q = (w >> (j * 4)) & 15;
        float v = s * (float)(q - z);
        __nv_bfloat16 h = __float2bfloat16_rn(v);
        hi.h[j] = h;
        lo.h[j] = __float2bfloat16_rn(v - __bfloat162float(h));
    }

    int k0 = kw << 3;
    size_t off = ((size_t)(n >> 7) * KTILES + (k0 >> 6)) * B_TILE_BYTES
               + swz128((uint32_t)((n & 127) * 128 + (k0 & 63) * 2));
    *reinterpret_cast<uint4*>(reinterpret_cast<char*>(g_whi) + off) = hi.u;
    *reinterpret_cast<uint4*>(reinterpret_cast<char*>(g_wlo) + off) = lo.u;
}

// ---------------------------------------------------------------------------
// Pass 3: mma.sync GEMM, 128x128 tile, 4-stage cp.async.bulk pipeline
// ---------------------------------------------------------------------------
__global__ __launch_bounds__(NTHREADS, 1)
void gemm_mma(const float* __restrict__ bias, float* __restrict__ out) {
    extern __shared__ char smem[];
    const uint32_t sb = smem_u32(smem);
    const int tid = threadIdx.x;

    const uint32_t mbar0 = sb;   // full[s]=sb+s*16, empty[s]=sb+s*16+8

    if (tid == 0) {
        #pragma unroll
        for (int s = 0; s < STAGES; s++) {
            mbar_init(mbar0 + s * 16, 1);       // full: tx-based
            mbar_init(mbar0 + s * 16 + 8, 8);   // empty: one arrive per warp
        }
    }
    __syncthreads();

    const size_t a_base = (size_t)blockIdx.y * KTILES * A_TILE_BYTES;
    const size_t b_base = (size_t)blockIdx.x * KTILES * B_TILE_BYTES;

    if (tid == 0) {
        #pragma unroll
        for (int s = 0; s < STAGES; s++) {   // prologue: seg 0, tiles 0..3
            uint32_t full = mbar0 + s * 16;
            uint32_t a_s = sb + SMEM_HDR + s * STAGE_BYTES;
            mbar_expect_tx(full, STAGE_BYTES);
            bulk_g2s(a_s, (const char*)g_xhi + a_base + (size_t)s * A_TILE_BYTES,
                     A_TILE_BYTES, full);
            bulk_g2s(a_s + A_TILE_BYTES, (const char*)g_whi + b_base + (size_t)s * B_TILE_BYTES,
                     B_TILE_BYTES, full);
        }
    }

    const int warp = tid >> 5, lane = tid & 31;
    const int m0 = (warp >> 2) * 64;            // 2 warps in M
    const int n0 = (warp & 3) * 32;             // 4 warps in N
    const int laneA_r  = lane & 15;
    const int laneA_kc = (lane >> 4) & 1;
    const int laneB_r  = (lane & 7) | ((lane >> 4) << 3);
    const int laneB_kc = (lane >> 3) & 1;

    float acc[4][4][4];
    #pragma unroll
    for (int i = 0; i < 4; i++)
        #pragma unroll
        for (int j = 0; j < 4; j++)
            #pragma unroll
            for (int c = 0; c < 4; c++)
                acc[i][j][c] = 0.0f;

    for (int it = 0; it < NTILES; it++) {
        const int st = it & (STAGES - 1);
        const uint32_t ph = (uint32_t)(it >> 2) & 1u;
        const uint32_t full  = mbar0 + st * 16;
        const uint32_t empty = full + 8;
        const uint32_t a_s = sb + SMEM_HDR + st * STAGE_BYTES;
        const uint32_t b_s = a_s + A_TILE_BYTES;

        mbar_wait(full, ph);

        #pragma unroll
        for (int ks = 0; ks < 4; ks++) {
            uint32_t a[4][4];
            #pragma unroll
            for (int mi = 0; mi < 4; mi++) {
                uint32_t byte = (uint32_t)((m0 + mi * 16 + laneA_r) * 128
                                           + ks * 32 + laneA_kc * 16);
                ldsm_x4(a[mi], a_s + swz128(byte));
            }
            uint32_t b[4][2];
            #pragma unroll
            for (int bi = 0; bi < 2; bi++) {
                uint32_t r[4];
                uint32_t byte = (uint32_t)((n0 + bi * 16 + laneB_r) * 128
                                           + ks * 32 + laneB_kc * 16);
                ldsm_x4(r, b_s + swz128(byte));
                b[2 * bi][0] = r[0]; b[2 * bi][1] = r[1];
                b[2 * bi + 1][0] = r[2]; b[2 * bi + 1][1] = r[3];
            }
            #pragma unroll
            for (int mi = 0; mi < 4; mi++)
                #pragma unroll
                for (int ni = 0; ni < 4; ni++)
                    mma_16816(acc[mi][ni], a[mi], b[ni]);
        }

        if (lane == 0) mbar_arrive(empty);

        if (tid == 0) {
            const int pre = it + STAGES;
            if (pre < NTILES) {
                mbar_wait(empty, ph);      // all 8 warps done with this stage
                const int tk = pre & (KTILES - 1);
                const char* asrc = (pre < 2 * KTILES) ? (const char*)g_xhi
                                                      : (const char*)g_xlo;
                const char* bsrc = (pre < KTILES) ? (const char*)g_whi
                                 : (pre < 2 * KTILES) ? (const char*)g_wlo
                                                      : (const char*)g_whi;
                mbar_expect_tx(full, STAGE_BYTES);
                bulk_g2s(a_s, asrc + a_base + (size_t)tk * A_TILE_BYTES, A_TILE_BYTES, full);
                bulk_g2s(b_s, bsrc + b_base + (size_t)tk * B_TILE_BYTES, B_TILE_BYTES, full);
            }
        }
    }

    // epilogue: bias + store (fp32 exact)
    const int bm = blockIdx.y * BM;
    const int bn = blockIdx.x * BN;
    const int g4 = lane >> 2;       // 0..7
    const int t4 = lane & 3;        // 0..3
    #pragma unroll
    for (int mi = 0; mi < 4; mi++) {
        const int row0 = bm + m0 + mi * 16 + g4;
        #pragma unroll
        for (int ni = 0; ni < 4; ni++) {
            const int col = bn + n0 + ni * 8 + t4 * 2;
            const float2 bz = *reinterpret_cast<const float2*>(&bias[col]);
            float2 v0, v1;
            v0.x = acc[mi][ni][0] + bz.x;
            v0.y = acc[mi][ni][1] + bz.y;
            v1.x = acc[mi][ni][2] + bz.x;
            v1.y = acc[mi][ni][3] + bz.y;
            *reinterpret_cast<float2*>(&out[(size_t)row0 * NDIM + col]) = v0;
            *reinterpret_cast<float2*>(&out[(size_t)(row0 + 8) * NDIM + col]) = v1;
        }
    }
}

// ---------------------------------------------------------------------------
extern "C" void kernel_launch(void* const* d_in, const int* in_sizes, int n_in,
                              void* d_out, int out_size)
{
    const float* x    = (const float*)d_in[0];
    const int*   qw   = (const int*)  d_in[1];
    const int*   qz   = (const int*)  d_in[2];
    const float* sc   = (const float*)d_in[3];
    const float* bias = (const float*)d_in[4];
    float*       out  = (float*)d_out;

    const int M = in_sizes[0] / KDIM;   // 8192

    split_x<<<(int)(((size_t)M * KDIM / 8 + 255) / 256), 256>>>(x, M);
    dequant_w<<<(KDIM / 8) * NDIM / 256, 256>>>(qw, qz, sc);

    cudaFuncSetAttribute(gemm_mma, cudaFuncAttributeMaxDynamicSharedMemorySize, SMEM_TOTAL);
    dim3 grid(NDIM / BN, M / BM);       // (32, 64)
    gemm_mma<<<grid, NTHREADS, SMEM_TOTAL>>>(bias, out);
}

// round 4
// speedup vs baseline: 3.1088x; 1.0206x over previous
#include <cuda_runtime.h>
#include <cuda_bf16.h>
#include <cstdint>

// GPTQ 4-bit linear, v4: bf16 mma.sync with exact-integer weights + per-group rescale.
//   Pass 1: split x (fp32) -> x_hi + x_lo (bf16), pre-tiled + SW128-swizzled.
//   Pass 2: GEMM: per K-group g (128 k), acc_g = (x_hi + x_lo) @ (q - z)  [exact bf16 ints],
//           then total += s[g, col] * acc_g in fp32 registers. Bias in epilogue.
//   Weights are dequantized from raw qweight nibbles in-kernel (no W scratch).

#define KDIM 4096
#define NDIM 4096
#define MMAX 8192
#define BM 128
#define BN 128
#define BK 64
#define STAGES 4
#define NTHREADS 256
#define KTILES (KDIM / BK)              // 64 k-tiles
#define A_TILE_BYTES (BM * BK * 2)      // 16384 (per hi/lo matrix)
#define BP_BYTES (BN * BK / 2)          // 4096 packed nibbles
#define BD_BYTES (BN * BK * 2)          // 16384 dequantized bf16
#define TX_BYTES (2 * A_TILE_BYTES + BP_BYTES)   // 36864 per-stage bulk payload
#define STAGE_BYTES (TX_BYTES + BD_BYTES)        // 53248 (52 KB, 1KB-multiple)
#define SMEM_HDR 1024
#define SMEM_TOTAL (SMEM_HDR + STAGES * STAGE_BYTES)  // 214016

__device__ __align__(1024) __nv_bfloat16 g_xhi[(size_t)MMAX * KDIM];
__device__ __align__(1024) __nv_bfloat16 g_xlo[(size_t)MMAX * KDIM];

__device__ __forceinline__ uint32_t swz128(uint32_t off) {
    return off ^ ((off >> 3) & 0x70);
}
__device__ __forceinline__ uint32_t smem_u32(const void* p) {
    uint32_t a;
    asm("{ .reg .u64 t; cvta.to.shared.u64 t, %1; cvt.u32.u64 %0, t; }" : "=r"(a) : "l"(p));
    return a;
}
__device__ __forceinline__ void mbar_init(uint32_t mbar, uint32_t count) {
    asm volatile("mbarrier.init.shared.b64 [%0], %1;" :: "r"(mbar), "r"(count) : "memory");
}
__device__ __forceinline__ void mbar_expect_tx(uint32_t mbar, uint32_t bytes) {
    asm volatile("mbarrier.arrive.expect_tx.shared.b64 _, [%0], %1;" :: "r"(mbar), "r"(bytes) : "memory");
}
__device__ __forceinline__ void mbar_arrive(uint32_t mbar) {
    asm volatile("mbarrier.arrive.shared.b64 _, [%0];" :: "r"(mbar) : "memory");
}
__device__ __forceinline__ void mbar_wait(uint32_t mbar, uint32_t parity) {
    asm volatile(
        "{\n\t.reg .pred P;\n\t"
        "WAIT_%=:\n\t"
        "mbarrier.try_wait.parity.acquire.cta.shared::cta.b64 P, [%0], %1, 0x989680;\n\t"
        "@!P bra WAIT_%=;\n\t}"
        :: "r"(mbar), "r"(parity) : "memory");
}
__device__ __forceinline__ void bulk_g2s(uint32_t dst, const void* src, uint32_t bytes, uint32_t mbar) {
    asm volatile(
        "cp.async.bulk.shared::cluster.global.mbarrier::complete_tx::bytes [%0], [%1], %2, [%3];"
        :: "r"(dst), "l"(src), "r"(bytes), "r"(mbar) : "memory");
}
__device__ __forceinline__ void ldsm_x4(uint32_t* r, uint32_t addr) {
    asm volatile("ldmatrix.sync.aligned.m8n8.x4.shared.b16 {%0,%1,%2,%3}, [%4];"
                 : "=r"(r[0]), "=r"(r[1]), "=r"(r[2]), "=r"(r[3]) : "r"(addr));
}
__device__ __forceinline__ void mma_16816(float* c, const uint32_t* a, const uint32_t* b) {
    asm volatile(
        "mma.sync.aligned.m16n8k16.row.col.f32.bf16.bf16.f32 "
        "{%0,%1,%2,%3}, {%4,%5,%6,%7}, {%8,%9}, {%0,%1,%2,%3};"
        : "+f"(c[0]), "+f"(c[1]), "+f"(c[2]), "+f"(c[3])
        : "r"(a[0]), "r"(a[1]), "r"(a[2]), "r"(a[3]), "r"(b[0]), "r"(b[1]));
}

// ---------------------------------------------------------------------------
// Pass 1: split x into bf16 hi/lo, pre-tiled + swizzled
// ---------------------------------------------------------------------------
__global__ void split_x(const float* __restrict__ x, int M) {
    size_t idx = (size_t)blockIdx.x * blockDim.x + threadIdx.x;  // one per 8 elems
    size_t total = (size_t)M * KDIM / 8;
    if (idx >= total) return;
    int m  = (int)(idx >> 9);
    int k0 = ((int)idx & 511) << 3;

    const float* src = x + (size_t)m * KDIM + k0;
    float4 v0 = *reinterpret_cast<const float4*>(src);
    float4 v1 = *reinterpret_cast<const float4*>(src + 4);
    float v[8] = {v0.x, v0.y, v0.z, v0.w, v1.x, v1.y, v1.z, v1.w};

    union { __nv_bfloat16 h[8]; uint4 u; } hi, lo;
    #pragma unroll
    for (int j = 0; j < 8; j++) {
        __nv_bfloat16 h = __float2bfloat16_rn(v[j]);
        hi.h[j] = h;
        lo.h[j] = __float2bfloat16_rn(v[j] - __bfloat162float(h));
    }

    size_t off = ((size_t)(m >> 7) * KTILES + (k0 >> 6)) * A_TILE_BYTES
               + swz128((uint32_t)((m & 127) * 128 + (k0 & 63) * 2));
    *reinterpret_cast<uint4*>(reinterpret_cast<char*>(g_xhi) + off) = hi.u;
    *reinterpret_cast<uint4*>(reinterpret_cast<char*>(g_xlo) + off) = lo.u;
}

// ---------------------------------------------------------------------------
// Pass 2: GEMM with in-kernel dequant + per-group rescale
// ---------------------------------------------------------------------------
__global__ __launch_bounds__(NTHREADS, 1)
void gemm_mma(const int* __restrict__ qw, const int* __restrict__ qz,
              const float* __restrict__ sc, const float* __restrict__ bias,
              float* __restrict__ out) {
    extern __shared__ char smem[];
    const uint32_t sb = smem_u32(smem);
    const int tid = threadIdx.x;

    const uint32_t mbar0 = sb;   // full[s]=sb+s*16, empty[s]=sb+s*16+8

    if (tid == 0) {
        #pragma unroll
        for (int s = 0; s < STAGES; s++) {
            mbar_init(mbar0 + s * 16, 1);       // full: tx-based
            mbar_init(mbar0 + s * 16 + 8, 8);   // empty: one arrive per warp
        }
    }
    __syncthreads();

    const int bm = blockIdx.y * BM;
    const int bn = blockIdx.x * BN;
    const size_t a_base = (size_t)blockIdx.y * KTILES * A_TILE_BYTES;

    // prologue: fill all 4 stages (k-tiles 0..3)
    if (tid == 0) {
        #pragma unroll
        for (int s = 0; s < STAGES; s++) {
            uint32_t full = mbar0 + s * 16;
            uint32_t st_s = sb + SMEM_HDR + s * STAGE_BYTES;
            mbar_expect_tx(full, TX_BYTES);
            bulk_g2s(st_s, (const char*)g_xhi + a_base + (size_t)s * A_TILE_BYTES,
                     A_TILE_BYTES, full);
            bulk_g2s(st_s + A_TILE_BYTES, (const char*)g_xlo + a_base + (size_t)s * A_TILE_BYTES,
                     A_TILE_BYTES, full);
            #pragma unroll
            for (int r = 0; r < 8; r++)
                bulk_g2s(st_s + 2 * A_TILE_BYTES + r * 512,
                         (const char*)qw + ((size_t)(s * 8 + r) * NDIM + bn) * 4, 512, full);
        }
    }

    const int warp = tid >> 5, lane = tid & 31;
    const int m0 = (warp >> 2) * 64;            // 2 warps in M
    const int n0 = (warp & 3) * 32;             // 4 warps in N
    const int t4 = lane & 3;
    const int laneA_r  = lane & 15;
    const int laneA_kc = (lane >> 4) & 1;
    const int laneB_r  = (lane & 7) | ((lane >> 4) << 3);
    const int laneB_kc = (lane >> 3) & 1;

    // dequant mapping: 256 threads -> 128 cols x 2 halves (4 packed words each)
    const int dq_col  = tid & 127;
    const int dq_half = tid >> 7;
    const int gcol = bn + dq_col;
    const int zshift = (gcol & 7) * 4;
    const int* zrow = qz + (gcol >> 3);

    float total[4][4][4];
    float accg[4][4][4];
    #pragma unroll
    for (int i = 0; i < 4; i++)
        #pragma unroll
        for (int j = 0; j < 4; j++)
            #pragma unroll
            for (int c = 0; c < 4; c++) { total[i][j][c] = 0.0f; accg[i][j][c] = 0.0f; }

    int zcur = 0;
    float2 sv[4];

    for (int it = 0; it < KTILES; it++) {
        const int st = it & (STAGES - 1);
        const uint32_t ph = (uint32_t)(it >> 2) & 1u;
        const uint32_t full  = mbar0 + st * 16;
        const uint32_t empty = full + 8;
        const uint32_t st_s = sb + SMEM_HDR + st * STAGE_BYTES;
        const uint32_t bd_s = st_s + TX_BYTES;

        if ((it & 1) == 0) {   // group start: fetch zero + scales (hide latency)
            const int g = it >> 1;
            zcur = ((zrow[g * (NDIM / 8)] >> zshift) & 15) + 1;
            #pragma unroll
            for (int ni = 0; ni < 4; ni++)
                sv[ni] = *reinterpret_cast<const float2*>(
                    &sc[(size_t)g * NDIM + bn + n0 + ni * 8 + t4 * 2]);
        }

        mbar_wait(full, ph);

        // dequant packed nibbles -> bf16 ints in smem
        {
            const char* bp = smem + SMEM_HDR + st * STAGE_BYTES + 2 * A_TILE_BYTES;
            #pragma unroll
            for (int j = 0; j < 4; j++) {
                const int wr = dq_half * 4 + j;
                uint32_t w = *reinterpret_cast<const uint32_t*>(bp + wr * 512 + dq_col * 4);
                union { __nv_bfloat16 h[8]; uint4 u; } d;
                #pragma unroll
                for (int nb = 0; nb < 8; nb++) {
                    int q = (int)((w >> (4 * nb)) & 15u);
                    d.h[nb] = __float2bfloat16_rn((float)(q - zcur));
                }
                uint32_t byte = (uint32_t)(dq_col * 128 + (dq_half * 32 + j * 8) * 2);
                *reinterpret_cast<uint4*>(smem + SMEM_HDR + st * STAGE_BYTES + TX_BYTES
                                          + swz128(byte)) = d.u;
            }
        }
        __syncthreads();

        #pragma unroll
        for (int ks = 0; ks < 4; ks++) {
            uint32_t ah[4][4], al[4][4];
            #pragma unroll
            for (int mi = 0; mi < 4; mi++) {
                uint32_t byte = (uint32_t)((m0 + mi * 16 + laneA_r) * 128
                                           + ks * 32 + laneA_kc * 16);
                ldsm_x4(ah[mi], st_s + swz128(byte));
                ldsm_x4(al[mi], st_s + A_TILE_BYTES + swz128(byte));
            }
            uint32_t b[4][2];
            #pragma unroll
            for (int bi = 0; bi < 2; bi++) {
                uint32_t r[4];
                uint32_t byte = (uint32_t)((n0 + bi * 16 + laneB_r) * 128
                                           + ks * 32 + laneB_kc * 16);
                ldsm_x4(r, bd_s + swz128(byte));
                b[2 * bi][0] = r[0]; b[2 * bi][1] = r[1];
                b[2 * bi + 1][0] = r[2]; b[2 * bi + 1][1] = r[3];
            }
            #pragma unroll
            for (int mi = 0; mi < 4; mi++)
                #pragma unroll
                for (int ni = 0; ni < 4; ni++) {
                    mma_16816(accg[mi][ni], ah[mi], b[ni]);
                    mma_16816(accg[mi][ni], al[mi], b[ni]);
                }
        }

        if (it & 1) {   // group end: rescale into total
            #pragma unroll
            for (int mi = 0; mi < 4; mi++)
                #pragma unroll
                for (int ni = 0; ni < 4; ni++) {
                    total[mi][ni][0] = fmaf(sv[ni].x, accg[mi][ni][0], total[mi][ni][0]);
                    total[mi][ni][1] = fmaf(sv[ni].y, accg[mi][ni][1], total[mi][ni][1]);
                    total[mi][ni][2] = fmaf(sv[ni].x, accg[mi][ni][2], total[mi][ni][2]);
                    total[mi][ni][3] = fmaf(sv[ni].y, accg[mi][ni][3], total[mi][ni][3]);
                    accg[mi][ni][0] = 0.0f; accg[mi][ni][1] = 0.0f;
                    accg[mi][ni][2] = 0.0f; accg[mi][ni][3] = 0.0f;
                }
        }

        if (lane == 0) mbar_arrive(empty);

        if (tid == 0) {
            const int pre = it + STAGES;
            if (pre < KTILES) {
                mbar_wait(empty, ph);
                mbar_expect_tx(full, TX_BYTES);
                bulk_g2s(st_s, (const char*)g_xhi + a_base + (size_t)pre * A_TILE_BYTES,
                         A_TILE_BYTES, full);
                bulk_g2s(st_s + A_TILE_BYTES,
                         (const char*)g_xlo + a_base + (size_t)pre * A_TILE_BYTES,
                         A_TILE_BYTES, full);
                #pragma unroll
                for (int r = 0; r < 8; r++)
                    bulk_g2s(st_s + 2 * A_TILE_BYTES + r * 512,
                             (const char*)qw + ((size_t)(pre * 8 + r) * NDIM + bn) * 4,
                             512, full);
            }
        }
    }

    // epilogue: bias + store
    const int g4 = lane >> 2;
    #pragma unroll
    for (int mi = 0; mi < 4; mi++) {
        const int row0 = bm + m0 + mi * 16 + g4;
        #pragma unroll
        for (int ni = 0; ni < 4; ni++) {
            const int col = bn + n0 + ni * 8 + t4 * 2;
            const float2 bz = *reinterpret_cast<const float2*>(&bias[col]);
            float2 v0, v1;
            v0.x = total[mi][ni][0] + bz.x;
            v0.y = total[mi][ni][1] + bz.y;
            v1.x = total[mi][ni][2] + bz.x;
            v1.y = total[mi][ni][3] + bz.y;
            *reinterpret_cast<float2*>(&out[(size_t)row0 * NDIM + col]) = v0;
            *reinterpret_cast<float2*>(&out[(size_t)(row0 + 8) * NDIM + col]) = v1;
        }
    }
}

// ---------------------------------------------------------------------------
extern "C" void kernel_launch(void* const* d_in, const int* in_sizes, int n_in,
                              void* d_out, int out_size)
{
    const float* x    = (const float*)d_in[0];
    const int*   qw   = (const int*)  d_in[1];
    const int*   qz   = (const int*)  d_in[2];
    const float* sc   = (const float*)d_in[3];
    const float* bias = (const float*)d_in[4];
    float*       out  = (float*)d_out;

    const int M = in_sizes[0] / KDIM;   // 8192

    split_x<<<(int)(((size_t)M * KDIM / 8 + 255) / 256), 256>>>(x, M);

    cudaFuncSetAttribute(gemm_mma, cudaFuncAttributeMaxDynamicSharedMemorySize, SMEM_TOTAL);
    dim3 grid(NDIM / BN, M / BM);       // (32, 64)
    gemm_mma<<<grid, NTHREADS, SMEM_TOTAL>>>(qw, qz, sc, bias, out);
}